// round 5
// baseline (speedup 1.0000x reference)
#include <cuda_runtime.h>

// StyleGAN2 modulated conv2d 3x3, B=8, Ci=Co=512, H=W=32, fp32.
// Implicit GEMM on CUDA cores using packed fma.rn.f32x2 (FFMA2).
// Prologue kernels compute w2[o,i] = scale^2 * sum_k w^2 and
// coef[b,o] = scale / sqrt(sum_i y^2 * w2 + 1e-8); main kernel computes
// conv(x*y_s, w_raw) and multiplies by coef (scale folded into coef).

#define B_   8
#define CI_  512
#define CO_  512
#define H_   32
#define W_   32
#define CK   8      // Ci chunk per K-iteration
#define COT  64     // Co tile per CTA
#define ST   16     // spatial tile (16x16 output pixels)
#define XROWS 18
#define XSTRIDE 24  // padded smem col stride (keeps 16B alignment per row)

__device__ float g_w2[CO_ * CI_];
__device__ float g_coef[B_ * CO_];

typedef unsigned long long u64;

__device__ __forceinline__ u64 pack2(float lo, float hi) {
    u64 r; asm("mov.b64 %0, {%1, %2};" : "=l"(r) : "f"(lo), "f"(hi)); return r;
}
__device__ __forceinline__ void fma2(u64 &d, u64 a, u64 b) {
    asm("fma.rn.f32x2 %0, %1, %2, %0;" : "+l"(d) : "l"(a), "l"(b));
}
__device__ __forceinline__ void unpack2(u64 v, float &lo, float &hi) {
    asm("mov.b64 {%0, %1}, %2;" : "=f"(lo), "=f"(hi) : "l"(v));
}

// w2[o*CI+i] = (1/4608) * sum_{k=0..8} weight[o,i,k]^2
__global__ void w2_kernel(const float* __restrict__ w) {
    int idx = blockIdx.x * 256 + threadIdx.x;
    if (idx >= CO_ * CI_) return;
    const float* p = w + idx * 9;
    float s = 0.f;
#pragma unroll
    for (int k = 0; k < 9; k++) { float v = p[k]; s += v * v; }
    g_w2[idx] = s * (1.0f / 4608.0f);
}

// coef[b*CO+o] = scale * rsqrt(sum_i y[b,i]^2 * w2[o,i] + 1e-8), one warp per (b,o)
__global__ void coef_kernel(const float* __restrict__ y_s) {
    int gt = blockIdx.x * 256 + threadIdx.x;
    int warp = gt >> 5, lane = gt & 31;
    if (warp >= B_ * CO_) return;
    int b = warp >> 9, o = warp & (CO_ - 1);
    const float* yrow = y_s + b * CI_;
    const float* wrow = g_w2 + o * CI_;
    float acc = 0.f;
    for (int i = lane; i < CI_; i += 32) {
        float y = yrow[i];
        acc += y * y * wrow[i];
    }
#pragma unroll
    for (int off = 16; off; off >>= 1) acc += __shfl_xor_sync(0xffffffffu, acc, off);
    if (lane == 0) g_coef[warp] = 0.0147313913f /* 1/sqrt(4608) */ * rsqrtf(acc + 1e-8f);
}

__global__ __launch_bounds__(256, 2) void conv_kernel(
    const float* __restrict__ x, const float* __restrict__ y_s,
    const float* __restrict__ w, const float* __restrict__ bias,
    float* __restrict__ out)
{
    __shared__ __align__(16) float XS[CK * XROWS * XSTRIDE]; // 13.5 KB
    __shared__ __align__(16) float WS[CK * 9 * COT];         // 18 KB

    int tid = threadIdx.x;
    int b   = blockIdx.z;
    int co0 = blockIdx.y * COT;
    int r0  = (blockIdx.x >> 1) * ST;
    int c0  = (blockIdx.x & 1) * ST;

    // warp spans Co dimension -> conflict-free x smem reads (2 addrs/warp)
    int cog = tid & 15;          // 16 groups of 4 output channels
    int pxg = tid >> 4;          // 16 groups of 4x4 output pixels
    int pr0 = (pxg >> 2) << 2;
    int pc0 = (pxg & 3) << 2;

    u64 acc[4][4][2];            // [co j][row rr][col-pair]
#pragma unroll
    for (int j = 0; j < 4; j++)
#pragma unroll
        for (int r = 0; r < 4; r++) { acc[j][r][0] = 0ULL; acc[j][r][1] = 0ULL; }

    const float* xb = x + b * (CI_ * H_ * W_);
    const float* yb = y_s + b * CI_;

    for (int ci0 = 0; ci0 < CI_; ci0 += CK) {
        __syncthreads();
        // --- X tile: CK x 18 x 18 halo, modulated by y_s at load ---
        for (int idx = tid; idx < CK * XROWS * 18; idx += 256) {
            int ck  = idx / (XROWS * 18);
            int rem = idx - ck * (XROWS * 18);
            int row = rem / 18;
            int col = rem - row * 18;
            int ir = r0 + row - 1;
            int ic = c0 + col - 1;
            float v = 0.f;
            if ((unsigned)ir < 32u && (unsigned)ic < 32u)
                v = __ldg(&xb[(ci0 + ck) * (H_ * W_) + ir * W_ + ic]) *
                    __ldg(&yb[ci0 + ck]);
            XS[ck * (XROWS * XSTRIDE) + row * XSTRIDE + col] = v;
        }
        // --- W tile: CK x 9 x COT (raw weights; scale folded into coef) ---
        for (int idx = tid; idx < CK * 9 * COT; idx += 256) {
            int co  = idx / (CK * 9);
            int rem = idx - co * (CK * 9);
            int ck  = rem / 9;
            int kp  = rem - ck * 9;
            float v = __ldg(&w[(co0 + co) * (CI_ * 9) + (ci0 + ck) * 9 + kp]);
            WS[ck * (9 * COT) + kp * COT + co] = v;
        }
        __syncthreads();

#pragma unroll 1
        for (int ck = 0; ck < CK; ck++) {
            const float* xs = XS + ck * (XROWS * XSTRIDE);
            const float* ws = WS + ck * (9 * COT);
#pragma unroll
            for (int kh = 0; kh < 3; kh++) {
                u64 wb[3][4];
#pragma unroll
                for (int kw = 0; kw < 3; kw++) {
                    float4 wv = *(const float4*)&ws[(kh * 3 + kw) * COT + cog * 4];
                    wb[kw][0] = pack2(wv.x, wv.x);
                    wb[kw][1] = pack2(wv.y, wv.y);
                    wb[kw][2] = pack2(wv.z, wv.z);
                    wb[kw][3] = pack2(wv.w, wv.w);
                }
#pragma unroll
                for (int rr = 0; rr < 4; rr++) {
                    const float* xr = xs + (pr0 + rr + kh) * XSTRIDE + pc0;
                    float4 xa  = *(const float4*)xr;
                    float2 xt  = *(const float2*)(xr + 4);
                    u64 xp0 = pack2(xa.x, xa.y);
                    u64 xp1 = pack2(xa.y, xa.z);
                    u64 xp2 = pack2(xa.z, xa.w);
                    u64 xp3 = pack2(xa.w, xt.x);
                    u64 xp4 = pack2(xt.x, xt.y);
                    // output cols (0,1) use x pairs at kw..kw+1; cols (2,3) at kw+2..kw+3
#pragma unroll
                    for (int j = 0; j < 4; j++) {
                        fma2(acc[j][rr][0], xp0, wb[0][j]);
                        fma2(acc[j][rr][1], xp2, wb[0][j]);
                        fma2(acc[j][rr][0], xp1, wb[1][j]);
                        fma2(acc[j][rr][1], xp3, wb[1][j]);
                        fma2(acc[j][rr][0], xp2, wb[2][j]);
                        fma2(acc[j][rr][1], xp4, wb[2][j]);
                    }
                }
            }
        }
    }

    // --- epilogue: demod + bias ---
    int r_base = r0 + pr0, c_base = c0 + pc0;
#pragma unroll
    for (int j = 0; j < 4; j++) {
        int co = co0 + cog * 4 + j;
        float cf = g_coef[b * CO_ + co];
        float bs = bias[co];
        float* orow = out + ((size_t)(b * CO_ + co) * H_ + r_base) * W_ + c_base;
#pragma unroll
        for (int rr = 0; rr < 4; rr++) {
            float o0, o1, o2, o3;
            unpack2(acc[j][rr][0], o0, o1);
            unpack2(acc[j][rr][1], o2, o3);
            float4 ov = make_float4(o0 * cf + bs, o1 * cf + bs,
                                    o2 * cf + bs, o3 * cf + bs);
            *(float4*)&orow[rr * W_] = ov;
        }
    }
}

extern "C" void kernel_launch(void* const* d_in, const int* in_sizes, int n_in,
                              void* d_out, int out_size) {
    const float* x    = (const float*)d_in[0];
    const float* y_s  = (const float*)d_in[1];
    const float* w    = (const float*)d_in[2];
    const float* bias = (const float*)d_in[3];
    float* out = (float*)d_out;

    w2_kernel<<<(CO_ * CI_ + 255) / 256, 256>>>(w);
    coef_kernel<<<(B_ * CO_ * 32 + 255) / 256, 256>>>(y_s);
    dim3 grid(4, CO_ / COT, B_);
    conv_kernel<<<grid, 256>>>(x, y_s, w, bias, out);
}

// round 17
// speedup vs baseline: 2.6015x; 2.6015x over previous
#include <cuda_runtime.h>
#include <cuda_bf16.h>
#include <cstdint>

// StyleGAN2 modulated conv2d 3x3, B=8, Ci=Co=512, H=W=32, fp32.
// mma.sync (HMMA) bf16 hi/lo-split implicit GEMM, 3 passes:
//   out = wh*xh + wl*xh + wh*xl  (wl*xl dropped, ~2^-18 rel)
// tcgen05 is unavailable: harness PTX targets compute_103 (no 'a').
// A = W[co][ci] (row-major, K contig) -> ldmatrix.x4
// B = Xt[pc][ci] (N-major, K contig)  -> ldmatrix.x2 (no .trans)
// 3x3 taps: kh picks padded row, kw shifts the B row base address.

#define B_   8
#define CI_  512
#define CO_  512
#define HW_  1024
#define PCW  40        // padded col count in x-transpose buffer
#define PRH  34        // padded rows

__device__ float g_w2[CO_ * CI_];
__device__ float g_coef[B_ * CO_];
__device__ __nv_bfloat16 g_xth[B_ * PRH * PCW * CI_];   // [b][pr][pc][ci]
__device__ __nv_bfloat16 g_xtl[B_ * PRH * PCW * CI_];
__device__ __nv_bfloat16 g_wh[9 * CO_ * CI_];           // [kp][co][ci]
__device__ __nv_bfloat16 g_wl[9 * CO_ * CI_];

typedef unsigned long long u64;
typedef unsigned int u32;

__device__ __forceinline__ u32 smem_u32(const void* p) {
    u32 a; asm("{ .reg .u64 t; cvta.to.shared.u64 t, %1; cvt.u32.u64 %0, t; }" : "=r"(a) : "l"(p));
    return a;
}
__device__ __forceinline__ void ldx4(u32* r, u32 a) {
    asm volatile("ldmatrix.sync.aligned.m8n8.x4.shared.b16 {%0,%1,%2,%3}, [%4];"
                 : "=r"(r[0]), "=r"(r[1]), "=r"(r[2]), "=r"(r[3]) : "r"(a));
}
__device__ __forceinline__ void ldx2(u32* r, u32 a) {
    asm volatile("ldmatrix.sync.aligned.m8n8.x2.shared.b16 {%0,%1}, [%2];"
                 : "=r"(r[0]), "=r"(r[1]) : "r"(a));
}
__device__ __forceinline__ void mma16816(float* c, const u32* A, const u32* B) {
    asm volatile(
        "mma.sync.aligned.m16n8k16.row.col.f32.bf16.bf16.f32 "
        "{%0,%1,%2,%3}, {%4,%5,%6,%7}, {%8,%9}, {%0,%1,%2,%3};"
        : "+f"(c[0]), "+f"(c[1]), "+f"(c[2]), "+f"(c[3])
        : "r"(A[0]), "r"(A[1]), "r"(A[2]), "r"(A[3]), "r"(B[0]), "r"(B[1]));
}

// ---------------- prologue kernels ----------------
__global__ void w2_kernel(const float* __restrict__ w) {
    int idx = blockIdx.x * 256 + threadIdx.x;
    if (idx >= CO_ * CI_) return;
    const float* p = w + idx * 9;
    float s = 0.f;
#pragma unroll
    for (int k = 0; k < 9; k++) { float v = p[k]; s += v * v; }
    g_w2[idx] = s * (1.0f / 4608.0f);
}

__global__ void coef_kernel(const float* __restrict__ y_s) {
    int gt = blockIdx.x * 256 + threadIdx.x;
    int warp = gt >> 5, lane = gt & 31;
    if (warp >= B_ * CO_) return;
    int b = warp >> 9, o = warp & (CO_ - 1);
    const float* yrow = y_s + b * CI_;
    const float* wrow = g_w2 + o * CI_;
    float acc = 0.f;
    for (int i = lane; i < CI_; i += 32) { float y = yrow[i]; acc += y * y * wrow[i]; }
#pragma unroll
    for (int off = 16; off; off >>= 1) acc += __shfl_xor_sync(0xffffffffu, acc, off);
    if (lane == 0) g_coef[warp] = 0.0147313913f * rsqrtf(acc + 1e-8f);
}

__global__ void zero_xt_kernel() {
    const int N4 = (B_ * PRH * PCW * CI_) / 8;
    int idx = blockIdx.x * 256 + threadIdx.x;
    uint4 z = make_uint4(0, 0, 0, 0);
    if (idx < N4) ((uint4*)g_xth)[idx] = z;
    else if (idx < 2 * N4) ((uint4*)g_xtl)[idx - N4] = z;
}

// transpose + modulate + hi/lo split: x[b,ci,r,c]*y -> xt[b][r+1][c+1][ci]
__global__ void xsplit_kernel(const float* __restrict__ x, const float* __restrict__ y_s) {
    __shared__ float T[32][33];
    int r = blockIdx.x, ci0b = blockIdx.y * 32, b = blockIdx.z;
    int tid = threadIdx.x;
    int ci_l = tid >> 3, cq = tid & 7;
    const float* xp = x + (((size_t)(b * CI_ + ci0b + ci_l)) * 32 + r) * 32 + cq * 4;
    float4 v = *(const float4*)xp;
    float y = y_s[b * CI_ + ci0b + ci_l];
    T[ci_l][cq * 4 + 0] = v.x * y;
    T[ci_l][cq * 4 + 1] = v.y * y;
    T[ci_l][cq * 4 + 2] = v.z * y;
    T[ci_l][cq * 4 + 3] = v.w * y;
    __syncthreads();
    int c = tid >> 3, g8 = tid & 7;
    size_t base = ((size_t)(b * PRH + r + 1) * PCW + (c + 1)) * CI_ + ci0b + g8 * 4;
#pragma unroll
    for (int j = 0; j < 4; j++) {
        float f = T[g8 * 4 + j][c];
        __nv_bfloat16 h = __float2bfloat16(f);
        g_xth[base + j] = h;
        g_xtl[base + j] = __float2bfloat16(f - __bfloat162float(h));
    }
}

__global__ void wsplit_kernel(const float* __restrict__ w) {
    int idx = blockIdx.x * 256 + threadIdx.x;
    if (idx >= CO_ * CI_) return;
    const float* p = w + (size_t)idx * 9;
#pragma unroll
    for (int kp = 0; kp < 9; kp++) {
        float f = p[kp];
        __nv_bfloat16 h = __float2bfloat16(f);
        g_wh[(size_t)kp * (CO_ * CI_) + idx] = h;
        g_wl[(size_t)kp * (CO_ * CI_) + idx] = __float2bfloat16(f - __bfloat162float(h));
    }
}

// ---------------- main mma.sync kernel ----------------
// SMEM (dynamic): XH[204*80] XL[204*80] WH[128*80] WL[128*80]
#define SM_XH 0
#define SM_XL 16320
#define SM_WH 32640
#define SM_WL 42880
#define SM_TOTAL 53120

__global__ __launch_bounds__(256, 2) void conv_mma_kernel(
    const float* __restrict__ bias, float* __restrict__ out)
{
    extern __shared__ char smem[];
    u32 sb = smem_u32(smem);
    int tid = threadIdx.x, lane = tid & 31, wid = tid >> 5;
    int wco = wid & 1;        // 0/1 -> 64-co half
    int wpx = wid >> 1;       // 0..3 -> image row within block
    int rg0 = blockIdx.x * 4; // output-row base (== padded-row base)
    int co0 = blockIdx.y * 128;
    int b   = blockIdx.z;

    float c[4][4][4];
#pragma unroll
    for (int mt = 0; mt < 4; mt++)
#pragma unroll
        for (int nt = 0; nt < 4; nt++)
#pragma unroll
            for (int k = 0; k < 4; k++) c[mt][nt][k] = 0.f;

    const __nv_bfloat16* xh_b = g_xth + (size_t)b * PRH * PCW * CI_;
    const __nv_bfloat16* xl_b = g_xtl + (size_t)b * PRH * PCW * CI_;

    // lane-dependent ldmatrix address components
    u32 aoff = (u32)((lane & 15) * 80 + (lane >> 4) * 16);
    u32 boff = (u32)((lane & 7) * 80 + ((lane >> 3) & 1) * 16);

    for (int ch = 0; ch < 16; ch++) {
        int ci0 = ch * 32;
        __syncthreads();   // all prior mma done reading X and W
        // ---- stage X: 6 padded rows x 34 pc x 32 ci, hi+lo ----
        for (int idx = tid; idx < 1632; idx += 256) {
            int prec = idx >= 816;
            int i = prec ? idx - 816 : idx;
            int row = i >> 2, q = i & 3;          // row = prl*34 + pc
            int prl = row / 34, pc = row - prl * 34;
            size_t g = ((size_t)((rg0 + prl) * PCW + pc)) * CI_ + ci0 + q * 8;
            uint4 v = *(const uint4*)((prec ? xl_b : xh_b) + g);
            *(uint4*)(smem + (prec ? SM_XL : SM_XH) + row * 80 + q * 16) = v;
        }
        for (int kp = 0; kp < 9; kp++) {
            if (kp) __syncthreads();   // prior mma done reading W
            // ---- stage W: 128 co x 32 ci, hi+lo ----
            for (int idx = tid; idx < 1024; idx += 256) {
                int prec = idx >= 512;
                int i = prec ? idx - 512 : idx;
                int row = i >> 2, q = i & 3;
                size_t g = (size_t)kp * (CO_ * CI_) + (size_t)(co0 + row) * CI_ + ci0 + q * 8;
                uint4 v = *(const uint4*)((prec ? g_wl : g_wh) + g);
                *(uint4*)(smem + (prec ? SM_WL : SM_WH) + row * 80 + q * 16) = v;
            }
            __syncthreads();
            int kh = kp / 3, kw = kp - kh * 3;
            u32 xrow0 = (u32)((wpx + kh) * 34 + kw);
#pragma unroll
            for (int ks = 0; ks < 2; ks++) {
                u32 bh[4][2], bl[4][2];
#pragma unroll
                for (int nt = 0; nt < 4; nt++) {
                    u32 ax = sb + SM_XH + (xrow0 + nt * 8) * 80 + ks * 32 + boff;
                    ldx2(bh[nt], ax);
                    ldx2(bl[nt], ax + (SM_XL - SM_XH));
                }
#pragma unroll
                for (int mt = 0; mt < 4; mt++) {
                    u32 aw = sb + SM_WH + (wco * 64 + mt * 16) * 80 + ks * 32 + aoff;
                    u32 aH[4], aL[4];
                    ldx4(aH, aw);
                    ldx4(aL, aw + (SM_WL - SM_WH));
#pragma unroll
                    for (int nt = 0; nt < 4; nt++) {
                        mma16816(c[mt][nt], aH, bh[nt]);
                        mma16816(c[mt][nt], aL, bh[nt]);
                        mma16816(c[mt][nt], aH, bl[nt]);
                    }
                }
            }
        }
    }

    // ---- epilogue: scale + bias, direct register -> gmem ----
    int q = lane & 3, rowq = lane >> 2;
    int r = rg0 + wpx;                       // output image row
#pragma unroll
    for (int mt = 0; mt < 4; mt++) {
        int co_a = co0 + wco * 64 + mt * 16 + rowq;
        int co_b = co_a + 8;
        float cfa = g_coef[b * CO_ + co_a], bsa = bias[co_a];
        float cfb = g_coef[b * CO_ + co_b], bsb = bias[co_b];
        float* oa = out + ((size_t)(b * CO_ + co_a)) * HW_ + r * 32;
        float* ob = out + ((size_t)(b * CO_ + co_b)) * HW_ + r * 32;
#pragma unroll
        for (int nt = 0; nt < 4; nt++) {
            int col = nt * 8 + q * 2;
            float2 va = make_float2(c[mt][nt][0] * cfa + bsa, c[mt][nt][1] * cfa + bsa);
            float2 vb = make_float2(c[mt][nt][2] * cfb + bsb, c[mt][nt][3] * cfb + bsb);
            *(float2*)&oa[col] = va;
            *(float2*)&ob[col] = vb;
        }
    }
}

extern "C" void kernel_launch(void* const* d_in, const int* in_sizes, int n_in,
                              void* d_out, int out_size) {
    const float* x    = (const float*)d_in[0];
    const float* y_s  = (const float*)d_in[1];
    const float* w    = (const float*)d_in[2];
    const float* bias = (const float*)d_in[3];
    float* out = (float*)d_out;

    w2_kernel<<<(CO_ * CI_ + 255) / 256, 256>>>(w);
    coef_kernel<<<(B_ * CO_ * 32 + 255) / 256, 256>>>(y_s);
    {
        int n4 = (B_ * PRH * PCW * CI_) / 8;
        zero_xt_kernel<<<(2 * n4 + 255) / 256, 256>>>();
    }
    xsplit_kernel<<<dim3(32, 16, 8), 256>>>(x, y_s);
    wsplit_kernel<<<(CO_ * CI_ + 255) / 256, 256>>>(w);

    cudaFuncSetAttribute(conv_mma_kernel, cudaFuncAttributeMaxDynamicSharedMemorySize, SM_TOTAL);
    conv_mma_kernel<<<dim3(8, 4, 8), 256, SM_TOTAL>>>(bias, out);
}